// round 17
// baseline (speedup 1.0000x reference)
#include <cuda_runtime.h>
#include <cuda_fp16.h>
#include <cstdint>
#include <math.h>

// ---------------- problem constants ----------------
#define N_TOK 4096
#define DIM   1024
#define FF    4096
#define NE    8
#define TEMP  0.9f
#define EPS   1e-5f
#define PADMAX 9216
#define GATE_BLOCKS 512
#define CONV_BLOCKS 2048      // w1-only conversion blocks in pre-GEMM kernel
#define G1_CONV_X 8           // extra grid.x slots in GEMM1 for w2 conversion
#define NSPLIT 4              // GEMM2 split-K factor

// ---------------- static device scratch ----------------
__device__ __half g_Xe[(size_t)PADMAX * DIM];    // fp16 gathered X
__device__ __half g_H [(size_t)PADMAX * FF];     // fp16 gelu acts
__device__ float  g_Yp[(size_t)NSPLIT * PADMAX * DIM];  // split-K partials
__device__ __half g_w1h[(size_t)NE * DIM * FF];  // fp16 w1
__device__ __half g_w2h[(size_t)NE * FF * DIM];  // fp16 w2
__device__ int   g_e0[N_TOK], g_e1[N_TOK];
__device__ float g_p0[N_TOK], g_p1[N_TOK];
__device__ int   g_pp0[N_TOK], g_pp1[N_TOK];
__device__ int   g_counts[NE], g_poff[NE], g_cursor[NE];

// ---------------- helpers ----------------
__device__ __forceinline__ uint32_t smem_u32(const void* p) {
    uint32_t a;
    asm("{ .reg .u64 t; cvta.to.shared.u64 t, %1; cvt.u32.u64 %0, t; }" : "=r"(a) : "l"(p));
    return a;
}
__device__ __forceinline__ void cp_async16(uint32_t dst, const void* src) {
    asm volatile("cp.async.cg.shared.global [%0], [%1], 16;" :: "r"(dst), "l"(src));
}
__device__ __forceinline__ uint32_t pack_f16x2(float lo, float hi) {
    uint32_t d;
    asm("cvt.rn.f16x2.f32 %0, %1, %2;" : "=r"(d) : "f"(hi), "f"(lo));
    return d;
}
__device__ __forceinline__ void ldmx4(uint32_t* r, uint32_t addr) {
    asm volatile("ldmatrix.sync.aligned.m8n8.x4.shared.b16 {%0,%1,%2,%3}, [%4];"
        : "=r"(r[0]), "=r"(r[1]), "=r"(r[2]), "=r"(r[3]) : "r"(addr));
}
__device__ __forceinline__ void ldmx4_t(uint32_t* r, uint32_t addr) {
    asm volatile("ldmatrix.sync.aligned.m8n8.x4.trans.shared.b16 {%0,%1,%2,%3}, [%4];"
        : "=r"(r[0]), "=r"(r[1]), "=r"(r[2]), "=r"(r[3]) : "r"(addr));
}
__device__ __forceinline__ void mma_f16(float* c, const uint32_t* a, const uint32_t* b) {
    asm volatile(
        "mma.sync.aligned.m16n8k16.row.col.f32.f16.f16.f32 "
        "{%0,%1,%2,%3}, {%4,%5,%6,%7}, {%8,%9}, {%0,%1,%2,%3};"
        : "+f"(c[0]), "+f"(c[1]), "+f"(c[2]), "+f"(c[3])
        : "r"(a[0]), "r"(a[1]), "r"(a[2]), "r"(a[3]), "r"(b[0]), "r"(b[1]));
}
__device__ __forceinline__ float warp_sum(float v) {
#pragma unroll
    for (int o = 16; o > 0; o >>= 1) v += __shfl_xor_sync(0xffffffffu, v, o);
    return v;
}

// ---------------- fused gate + w1 fp16 conversion ----------------
__global__ __launch_bounds__(256)
void fused_gate_convw1(const float* __restrict__ x,
                       const float* __restrict__ gw,
                       const float* __restrict__ gb,
                       const float* __restrict__ w1) {
    if (blockIdx.x < GATE_BLOCKS) {
        int warp = threadIdx.x >> 5, lane = threadIdx.x & 31;
        int t = blockIdx.x * 8 + warp;
        float acc[NE];
#pragma unroll
        for (int e = 0; e < NE; e++) acc[e] = 0.f;
        const float* xr = x + (size_t)t * DIM;
        for (int d = lane; d < DIM; d += 32) {
            float xv = xr[d];
            const float4* g4 = reinterpret_cast<const float4*>(gw + (size_t)d * NE);
            float4 a = g4[0], b = g4[1];
            acc[0] += xv * a.x; acc[1] += xv * a.y; acc[2] += xv * a.z; acc[3] += xv * a.w;
            acc[4] += xv * b.x; acc[5] += xv * b.y; acc[6] += xv * b.z; acc[7] += xv * b.w;
        }
#pragma unroll
        for (int e = 0; e < NE; e++) acc[e] = warp_sum(acc[e]);
        if (lane == 0) {
            float lg[NE];
#pragma unroll
            for (int e = 0; e < NE; e++) lg[e] = (acc[e] + gb[e]) / TEMP;
            int i0 = 0;
#pragma unroll
            for (int e = 1; e < NE; e++) if (lg[e] > lg[i0]) i0 = e;
            int i1 = (i0 == 0) ? 1 : 0;
#pragma unroll
            for (int e = 0; e < NE; e++)
                if (e != i0 && lg[e] > lg[i1]) i1 = e;
            float ev = expf(lg[i1] - lg[i0]);
            float s = 1.f + ev;
            g_e0[t] = i0; g_e1[t] = i1;
            g_p0[t] = 1.f / s; g_p1[t] = ev / s;
        }
    } else {
        const size_t total4 = (size_t)NE * DIM * FF / 4;
        size_t i = (size_t)(blockIdx.x - GATE_BLOCKS) * 256 + threadIdx.x;
        const float4* s1 = reinterpret_cast<const float4*>(w1);
        uint2* d1 = reinterpret_cast<uint2*>(g_w1h);
        for (size_t j = i; j < total4; j += (size_t)CONV_BLOCKS * 256) {
            float4 v = s1[j];
            d1[j] = make_uint2(pack_f16x2(v.x, v.y), pack_f16x2(v.z, v.w));
        }
    }
}

// ---------------- prefix: histogram + offsets ----------------
__global__ void prefix_kernel() {
    __shared__ int h[NE];
    int tid = threadIdx.x;
    if (tid < NE) h[tid] = 0;
    __syncthreads();
    for (int t = tid; t < N_TOK; t += 256) {
        atomicAdd(&h[g_e0[t]], 1);
        atomicAdd(&h[g_e1[t]], 1);
    }
    __syncthreads();
    if (tid == 0) {
        int s = 0;
#pragma unroll
        for (int e = 0; e < NE; e++) {
            g_counts[e] = h[e];
            g_poff[e] = s;
            s += ((h[e] + 127) / 128) * 128;
            g_cursor[e] = 0;
        }
    }
}

// ---------------- scatter: fused assign + gather ----------------
__global__ __launch_bounds__(256)
void scatter_kernel(const float* __restrict__ x) {
    int warp = threadIdx.x >> 5, lane = threadIdx.x & 31;
    int t = blockIdx.x * 8 + warp;
    int e0 = g_e0[t], e1 = g_e1[t];
    int p = 0, q = 0;
    if (lane == 0) {
        p = g_poff[e0] + atomicAdd(&g_cursor[e0], 1);
        q = g_poff[e1] + atomicAdd(&g_cursor[e1], 1);
        g_pp0[t] = p; g_pp1[t] = q;
    }
    p = __shfl_sync(0xffffffffu, p, 0);
    q = __shfl_sync(0xffffffffu, q, 0);
    const float4* xr = reinterpret_cast<const float4*>(x + (size_t)t * DIM);
    uint2* oa = reinterpret_cast<uint2*>(g_Xe) + (size_t)p * (DIM / 4);
    uint2* ob = reinterpret_cast<uint2*>(g_Xe) + (size_t)q * (DIM / 4);
#pragma unroll
    for (int i = 0; i < DIM / 128; i++) {
        int idx = lane + 32 * i;
        float4 v = xr[idx];
        uint2 h = make_uint2(pack_f16x2(v.x, v.y), pack_f16x2(v.z, v.w));
        oa[idx] = h;
        ob[idx] = h;
    }
}

// ---------------- fp16 mma.sync GEMM (all-fp16 operands, ldmatrix) ----------------
// CTA tile 128x128, K-chunk 1024 per CTA, BK=64, 3-stage pipeline, occupancy 2.
// GEMM1 (GELU=true):  A=g_Xe (LDA=1024), B=w1h, out=g_H with bias+gelu.
//                     extra grid.x slots carry w2 fp16 conversion.
// GEMM2 (GELU=false): split-K=4 over K=4096; A=g_H (LDA=4096), B=w2h,
//                     out=g_Yp[split] raw partials (bias added in LN).
#define STAGES 3
#define A_STRH 72                          // halfs: 64 + 8 pad
#define A_STGH (128 * A_STRH)
#define BSTRH_C 136                        // halfs: 128 + 8 pad
#define BSTGH_C (64 * BSTRH_C)
#define SMEM_FFN (STAGES * (A_STGH + BSTGH_C) * 2)   // 107520 B

template<int LDA, int NF, bool GELU>
__global__ __launch_bounds__(256, 2)
void ffn_mma_kernel(const float* __restrict__ bias_in,
                    const float* __restrict__ w2_src) {
    constexpr int WN  = 32;                // warp n-extent
    constexpr int NFR = 4;                 // n fragments
    constexpr int NXT = NF / 128;          // n-tiles
    constexpr int KCHUNK = 1024;           // K rows per CTA

    if (GELU && blockIdx.x >= (unsigned)NXT) {
        // w2 fp16 conversion, hidden under GEMM1 compute
        int cb = (blockIdx.x - NXT) + G1_CONV_X * (blockIdx.y + 32 * blockIdx.z);
        const size_t total4 = (size_t)NE * FF * DIM / 4;
        size_t i = (size_t)cb * 256 + threadIdx.x;
        const float4* s2 = reinterpret_cast<const float4*>(w2_src);
        uint2* d2 = reinterpret_cast<uint2*>(g_w2h);
        const size_t step = (size_t)G1_CONV_X * 32 * NE * 256;
        for (size_t j = i; j < total4; j += step) {
            float4 u = s2[j];
            d2[j] = make_uint2(pack_f16x2(u.x, u.y), pack_f16x2(u.z, u.w));
        }
        return;
    }

    int e = blockIdx.z;
    int cnt = g_counts[e];
    int mt = blockIdx.y;
    if (mt * 128 >= cnt) return;
    int m0 = g_poff[e] + mt * 128;

    int split, n0;
    if (GELU) { split = 0; n0 = blockIdx.x * 128; }
    else      { split = blockIdx.x >> 3; n0 = (blockIdx.x & 7) * 128; }

    const __half* Abase = (GELU ? g_Xe : g_H) + (size_t)m0 * LDA + split * KCHUNK;
    const __half* Bbase = (GELU ? g_w1h : g_w2h)
        + (size_t)e * LDA * NF + (size_t)split * KCHUNK * NF + n0;
    const float* bias = bias_in + (size_t)e * NF + n0;

    extern __shared__ __half smh[];
    __half* Asm = smh;
    __half* Bsm = smh + STAGES * A_STGH;
    uint32_t sA32 = smem_u32(Asm), sB32 = smem_u32(Bsm);

    int tid = threadIdx.x, wid = tid >> 5, lane = tid & 31;
    int warp_m = wid & 1, warp_n = wid >> 1;
    int group = lane >> 2, tig = lane & 3;
    int rw = lane & 7, quad = lane >> 3;

    auto load_stage = [&](int kt, int s) {
        int k0 = kt * 64;
        uint32_t aD = sA32 + s * (A_STGH * 2);
        uint32_t bD = sB32 + s * (BSTGH_C * 2);
#pragma unroll
        for (int i = 0; i < 4; i++) {            // A: 128 rows x 8 x 16B
            int idx = tid + i * 256;
            int row = idx >> 3, c8 = idx & 7;
            cp_async16(aD + row * (A_STRH * 2) + c8 * 16,
                       Abase + (size_t)row * LDA + k0 + c8 * 8);
        }
#pragma unroll
        for (int i = 0; i < 4; i++) {            // B: 64 rows x 16 x 16B
            int idx = tid + i * 256;
            int kk = idx >> 4, c8 = idx & 15;
            cp_async16(bD + (kk * BSTRH_C + c8 * 8) * 2,
                       Bbase + (size_t)(k0 + kk) * NF + c8 * 8);
        }
        asm volatile("cp.async.commit_group;");
    };

    float acc[4][NFR][4];
#pragma unroll
    for (int i = 0; i < 4; i++)
#pragma unroll
        for (int j = 0; j < NFR; j++)
#pragma unroll
            for (int q = 0; q < 4; q++) acc[i][j][q] = 0.f;

    const int ktiles = KCHUNK / 64;              // 16
    load_stage(0, 0);
    load_stage(1, 1);

    for (int kt = 0; kt < ktiles; kt++) {
        if (kt == ktiles - 1)
            asm volatile("cp.async.wait_group 0;" ::: "memory");
        else
            asm volatile("cp.async.wait_group 1;" ::: "memory");
        __syncthreads();

        if (kt + 2 < ktiles)
            load_stage(kt + 2, (kt + 2) % STAGES);

        int s = kt % STAGES;
        uint32_t aS = sA32 + s * (A_STGH * 2);
        uint32_t bS = sB32 + s * (BSTGH_C * 2);
#pragma unroll
        for (int ks = 0; ks < 4; ks++) {         // four k16 steps per K64 chunk
            int kb = ks * 16;
            uint32_t a[4][4], b[NFR][2];
#pragma unroll
            for (int m = 0; m < 4; m++) {
                int row = warp_m * 64 + m * 16 + rw + (quad & 1) * 8;
                int col = kb + (quad >> 1) * 8;
                ldmx4(a[m], aS + (row * A_STRH + col) * 2);
            }
#pragma unroll
            for (int n2 = 0; n2 < NFR / 2; n2++) {
                uint32_t r[4];
                int krow = kb + rw + (quad & 1) * 8;
                int col  = warp_n * WN + n2 * 16 + (quad >> 1) * 8;
                ldmx4_t(r, bS + (krow * BSTRH_C + col) * 2);
                b[2 * n2][0] = r[0]; b[2 * n2][1] = r[1];
                b[2 * n2 + 1][0] = r[2]; b[2 * n2 + 1][1] = r[3];
            }
#pragma unroll
            for (int m = 0; m < 4; m++)
#pragma unroll
                for (int n = 0; n < NFR; n++)
                    mma_f16(acc[m][n], a[m], b[n]);
        }
    }

    // epilogue
    float* yo = GELU ? nullptr : (g_Yp + (size_t)split * ((size_t)PADMAX * DIM));
#pragma unroll
    for (int m = 0; m < 4; m++) {
        int r0 = m0 + warp_m * 64 + m * 16 + group;
#pragma unroll
        for (int n = 0; n < NFR; n++) {
            int c = warp_n * WN + n * 8 + tig * 2;
            float bv0 = GELU ? bias[c] : 0.f;
            float bv1 = GELU ? bias[c + 1] : 0.f;
#pragma unroll
            for (int h = 0; h < 2; h++) {
                float v0 = acc[m][n][h * 2 + 0] + bv0;
                float v1 = acc[m][n][h * 2 + 1] + bv1;
                if (GELU) {
                    v0 = 0.5f * v0 * (1.f + erff(v0 * 0.70710678118654752f));
                    v1 = 0.5f * v1 * (1.f + erff(v1 * 0.70710678118654752f));
                    *reinterpret_cast<uint32_t*>(
                        g_H + (size_t)(r0 + h * 8) * NF + n0 + c) = pack_f16x2(v0, v1);
                } else {
                    *reinterpret_cast<float2*>(
                        yo + (size_t)(r0 + h * 8) * DIM + n0 + c) = make_float2(v0, v1);
                }
            }
        }
    }
}

// ---------------- combine (split-K reduce + bias) + LayerNorm ----------------
__global__ void ln_kernel(const float* __restrict__ b2,
                          const float* __restrict__ ln_g,
                          const float* __restrict__ ln_b,
                          float* __restrict__ out) {
    int t = blockIdx.x;
    __shared__ float sv[DIM];
    __shared__ float rs[8], rq[8];
    int tid = threadIdx.x;
    float p0 = g_p0[t], p1 = g_p1[t];
    size_t ra = (size_t)g_pp0[t] * DIM;
    size_t rb = (size_t)g_pp1[t] * DIM;
    const float* b2a = b2 + (size_t)g_e0[t] * DIM;
    const float* b2b = b2 + (size_t)g_e1[t] * DIM;
    const size_t SL = (size_t)PADMAX * DIM;
    float lsum = 0.f, lsq = 0.f;
    for (int d = tid; d < DIM; d += 256) {
        float s0 = g_Yp[ra + d] + g_Yp[SL + ra + d]
                 + g_Yp[2 * SL + ra + d] + g_Yp[3 * SL + ra + d] + b2a[d];
        float s1 = g_Yp[rb + d] + g_Yp[SL + rb + d]
                 + g_Yp[2 * SL + rb + d] + g_Yp[3 * SL + rb + d] + b2b[d];
        float v = p0 * s0 + p1 * s1;
        sv[d] = v;
        lsum += v; lsq += v * v;
    }
    lsum = warp_sum(lsum); lsq = warp_sum(lsq);
    int lane = tid & 31, wid = tid >> 5;
    if (lane == 0) { rs[wid] = lsum; rq[wid] = lsq; }
    __syncthreads();
    if (tid == 0) {
        float s = 0.f, q = 0.f;
#pragma unroll
        for (int w = 0; w < 8; w++) { s += rs[w]; q += rq[w]; }
        rs[0] = s; rq[0] = q;
    }
    __syncthreads();
    float mu  = rs[0] / DIM;
    float var = rq[0] / DIM - mu * mu;
    float inv = rsqrtf(var + EPS);
    float* outr = out + (size_t)t * DIM;
    for (int d = tid; d < DIM; d += 256)
        outr[d] = (sv[d] - mu) * inv * ln_g[d] + ln_b[d];
}

// ---------------- launch ----------------
extern "C" void kernel_launch(void* const* d_in, const int* in_sizes, int n_in,
                              void* d_out, int out_size) {
    const float* x      = (const float*)d_in[0];
    const float* gate_w = (const float*)d_in[1];
    const float* gate_b = (const float*)d_in[2];
    const float* w1     = (const float*)d_in[3];
    const float* b1     = (const float*)d_in[4];
    const float* w2     = (const float*)d_in[5];
    const float* b2     = (const float*)d_in[6];
    const float* ln_g   = (const float*)d_in[7];
    const float* ln_b   = (const float*)d_in[8];
    float* out = (float*)d_out;

    cudaFuncSetAttribute(ffn_mma_kernel<DIM, FF, true>,
                         cudaFuncAttributeMaxDynamicSharedMemorySize, SMEM_FFN);
    cudaFuncSetAttribute(ffn_mma_kernel<FF, DIM, false>,
                         cudaFuncAttributeMaxDynamicSharedMemorySize, SMEM_FFN);

    fused_gate_convw1<<<GATE_BLOCKS + CONV_BLOCKS, 256>>>(x, gate_w, gate_b, w1);
    prefix_kernel<<<1, 256>>>();
    scatter_kernel<<<N_TOK / 8, 256>>>(x);
    // GEMM1: 32 n-tiles + w2-conversion slots
    ffn_mma_kernel<DIM, FF, true ><<<dim3(FF / 128 + G1_CONV_X, 32, NE), 256, SMEM_FFN>>>(b1, w2);
    // GEMM2: split-K=4 x 8 n-tiles = 32 x-slots
    ffn_mma_kernel<FF, DIM, false><<<dim3(8 * NSPLIT, 32, NE), 256, SMEM_FFN>>>(b2, nullptr);
    ln_kernel<<<N_TOK, 256>>>(b2, ln_g, ln_b, out);
}